// round 8
// baseline (speedup 1.0000x reference)
#include <cuda_runtime.h>

#define T_DATA 20000
#define E_NO   2000
#define I_NO   500
#define SUB    12
#define CTAP   40            // tail beyond lag 40 contributes < 3e-6 rel
#define TT     80            // fused outputs per block
#define INLEN  144           // staged IN length; i -> t = t0 - 52 + i (136 real, pad 144)
#define SYNLEN 96            // syn j -> t = t0 - 13 + j

__device__ unsigned g_mask_e[SUB][64];
__device__ unsigned g_mask_i[SUB][16];
__device__ float g_INe[SUB][T_DATA];
__device__ float g_INi[SUB][T_DATA];
__device__ int g_pack_done;              // 0 at start of every run; reset by k_fused

__device__ __forceinline__ float sigm(float x) { return 1.f / (1.f + __expf(-x)); }

// ---------------- K1: pack (blocks 0-14) + IN = S @ C.T (all 1250 blocks) ----------
// Pack mapping: chunk (s, it): lane l loads float4 at elem it*128 + l*4; component c
// is bit l of word m = it*4 + c (bit l <-> element it*128 + l*4 + c).
__global__ __launch_bounds__(512) void k_reduce(const float* __restrict__ Se,
                                                const float* __restrict__ Si,
                                                const float* __restrict__ Ce,
                                                const float* __restrict__ Ci) {
    __shared__ unsigned long long sme2[32][13];
    __shared__ unsigned long long smi2[8][13];

    int warp = threadIdx.x >> 5, lane = threadIdx.x & 31;

    // --- phase A: blocks 0-14 pack the connectivity masks (240 warp tasks) ---
    if (blockIdx.x < 15) {
        int gw = blockIdx.x * 16 + warp;
        if (gw < SUB * 16) {                                 // e-chunks
            int s = gw >> 4, it = gw & 15;
            int base = it * 128 + lane * 4;
            float4 v = (base < E_NO) ? *(const float4*)(Ce + s * E_NO + base)
                                     : make_float4(0.f, 0.f, 0.f, 0.f);
            unsigned m0 = __ballot_sync(0xffffffffu, v.x != 0.f);
            unsigned m1 = __ballot_sync(0xffffffffu, v.y != 0.f);
            unsigned m2 = __ballot_sync(0xffffffffu, v.z != 0.f);
            unsigned m3 = __ballot_sync(0xffffffffu, v.w != 0.f);
            if (lane == 0) *(uint4*)&g_mask_e[s][it * 4] = make_uint4(m0, m1, m2, m3);
        } else {                                             // i-chunks
            int j = gw - SUB * 16;
            int s = j >> 2, it = j & 3;
            int base = it * 128 + lane * 4;
            float4 v = (base < I_NO) ? *(const float4*)(Ci + s * I_NO + base)
                                     : make_float4(0.f, 0.f, 0.f, 0.f);
            unsigned m0 = __ballot_sync(0xffffffffu, v.x != 0.f);
            unsigned m1 = __ballot_sync(0xffffffffu, v.y != 0.f);
            unsigned m2 = __ballot_sync(0xffffffffu, v.z != 0.f);
            unsigned m3 = __ballot_sync(0xffffffffu, v.w != 0.f);
            if (lane == 0) *(uint4*)&g_mask_i[s][it * 4] = make_uint4(m0, m1, m2, m3);
        }
        __syncthreads();
        if (threadIdx.x == 0) {
            __threadfence();
            atomicAdd(&g_pack_done, 1);
        }
    }

    // --- phase B: all blocks wait for masks (volatile poll, nanosleep backoff) ---
    if (threadIdx.x == 0) {
        const volatile int* p = &g_pack_done;
        while (*p < 15) __nanosleep(64);
    }
    __syncthreads();
    __threadfence();   // acquire: mask writes visible before smem staging

    for (int i = threadIdx.x; i < SUB * 32; i += blockDim.x) {
        int s = i >> 5, p = i & 31;
        sme2[p][s] = (unsigned long long)g_mask_e[s][2 * p] |
                     ((unsigned long long)g_mask_e[s][2 * p + 1] << 32);
    }
    for (int i = threadIdx.x; i < SUB * 8; i += blockDim.x) {
        int s = i >> 3, p = i & 7;
        smi2[p][s] = (unsigned long long)g_mask_i[s][2 * p] |
                     ((unsigned long long)g_mask_i[s][2 * p + 1] << 32);
    }
    __syncthreads();

    // --- phase C: row-per-warp ballot + popcount reduction (HBM-bound) ---
    int row = blockIdx.x * 16 + warp;
    if (row >= T_DATA) return;

    const float* re = Se + (size_t)row * E_NO;
    const float* ri = Si + (size_t)row * I_NO;
    int acc_e = 0, acc_i = 0;

#pragma unroll
    for (int ob = 0; ob < 2; ob++) {
        float4 v[8];
#pragma unroll
        for (int q = 0; q < 8; q++) {
            int base = (ob * 8 + q) * 128 + lane * 4;
            v[q] = (base < E_NO) ? *(const float4*)(re + base)
                                 : make_float4(0.f, 0.f, 0.f, 0.f);
        }
#pragma unroll
        for (int q = 0; q < 8; q++) {
            int it = ob * 8 + q;
            unsigned m0 = __ballot_sync(0xffffffffu, v[q].x != 0.f);
            unsigned m1 = __ballot_sync(0xffffffffu, v[q].y != 0.f);
            unsigned m2 = __ballot_sync(0xffffffffu, v[q].z != 0.f);
            unsigned m3 = __ballot_sync(0xffffffffu, v[q].w != 0.f);
            if (lane < SUB) {
                unsigned long long A = (unsigned long long)m0 | ((unsigned long long)m1 << 32);
                unsigned long long B = (unsigned long long)m2 | ((unsigned long long)m3 << 32);
                acc_e += __popcll(A & sme2[it * 2 + 0][lane]);
                acc_e += __popcll(B & sme2[it * 2 + 1][lane]);
            }
        }
    }
    {
        float4 v[4];
#pragma unroll
        for (int q = 0; q < 4; q++) {
            int base = q * 128 + lane * 4;
            v[q] = (base < I_NO) ? *(const float4*)(ri + base)
                                 : make_float4(0.f, 0.f, 0.f, 0.f);
        }
#pragma unroll
        for (int q = 0; q < 4; q++) {
            unsigned m0 = __ballot_sync(0xffffffffu, v[q].x != 0.f);
            unsigned m1 = __ballot_sync(0xffffffffu, v[q].y != 0.f);
            unsigned m2 = __ballot_sync(0xffffffffu, v[q].z != 0.f);
            unsigned m3 = __ballot_sync(0xffffffffu, v[q].w != 0.f);
            if (lane < SUB) {
                unsigned long long A = (unsigned long long)m0 | ((unsigned long long)m1 << 32);
                unsigned long long B = (unsigned long long)m2 | ((unsigned long long)m3 << 32);
                acc_i += __popcll(A & smi2[q * 2 + 0][lane]);
                acc_i += __popcll(B & smi2[q * 2 + 1][lane]);
            }
        }
    }
    if (lane < SUB) {
        g_INe[lane][row] = (float)acc_e;
        g_INi[lane][row] = (float)acc_i;
    }
}

// ---------------- K2: fused conv(40 taps) + wavefront recurrence, TT=80 ------------
__global__ __launch_bounds__(288) void k_fused(const float* __restrict__ Ws_syn,
                                               const float* __restrict__ Wns_syn,
                                               const float* __restrict__ Ds,
                                               const float* __restrict__ Dns,
                                               const float* __restrict__ C_den,
                                               const float* __restrict__ Ths_g,
                                               const float* __restrict__ Thns_g,
                                               const float* __restrict__ Ws_g,
                                               const float* __restrict__ Wns_g,
                                               float* __restrict__ out) {
    __shared__ float ker[SUB][4][CTAP];                  // [s][e_s,i_s,e_ns,i_ns][m]
    __shared__ __align__(16) float inbe[SUB][INLEN];
    __shared__ __align__(16) float inbi[SUB][INLEN];
    __shared__ float shs[SUB][SYNLEN], shn[SUB][SYNLEN];
    __shared__ float cw[SUB][SUB], cd[SUB][SUB];
    __shared__ float ths[SUB], thn[SUB], wsb[SUB], wnb[SUB];

    const int tid = threadIdx.x;
    const int warp = tid >> 5, lane = tid & 31;
    const int t0 = blockIdx.x * TT;

    if (blockIdx.x == 0 && tid == 0) g_pack_done = 0;    // reset for next graph replay

    // kernel coefficients: 12*4*40 = 1920 entries
    for (int id = tid; id < SUB * 4 * CTAP; id += 288) {
        int s = id / (4 * CTAP), rem = id % (4 * CTAP);
        int c = rem / CTAP, m = rem % CTAP;
        int ch = c & 1;
        const float* W = (c >= 2) ? Wns_syn : Ws_syn;
        const float* D = (c >= 2) ? Dns : Ds;
        float fk = (float)(CTAP - 1 - m);                // reversed: index m = lag CTAP-1-m
        float u = fmaxf(fk - expf(D[s * 2 + ch]), 0.f);
        float a = u, b = u * 0.60653065971f, cc = u * 0.36787944117f;
        ker[s][c][m] = W[s * 6 + ch] * a * expf(-a) + W[s * 6 + 2 + ch] * b * expf(-b) +
                       W[s * 6 + 4 + ch] * cc * expf(-cc);
    }
    if (tid < SUB * SUB) {
        float c = C_den[tid];
        cd[tid / SUB][tid % SUB] = c;
        cw[tid / SUB][tid % SUB] = c * Wns_g[tid % SUB];
    }
    if (tid < SUB) {
        ths[tid] = Ths_g[tid];
        thn[tid] = Thns_g[tid];
        wsb[tid] = Ws_g[tid];
        wnb[tid] = Wns_g[tid];
    }
    // stage IN: i in [0,144) -> t = t0 - 52 + i (zero-fill OOB and pad)
    for (int i = tid; i < SUB * INLEN; i += 288) {
        int s = i / INLEN, ii = i % INLEN;
        int g = t0 - 52 + ii;
        bool in = (g >= 0 && g < T_DATA && ii < 136);
        inbe[s][ii] = in ? g_INe[s][g] : 0.f;
        inbi[s][ii] = in ? g_INi[s][g] : 0.f;
    }
    __syncthreads();

    // conv: 288 threads = 12 subs x 24 groups of 4 outputs; syn[j] = sum_m ker[m]*IN[j+m]
    {
        int s = tid / 24, g = tid % 24;
        const float4* re4 = (const float4*)inbe[s];
        const float4* ri4 = (const float4*)inbi[s];
        const float* kes = ker[s][0];
        const float* kis = ker[s][1];
        const float* ken = ker[s][2];
        const float* kin = ker[s][3];

        float accs[4] = {0, 0, 0, 0}, accn[4] = {0, 0, 0, 0};
        float4 Ae = re4[g], Be = re4[g + 1];
        float4 Ai = ri4[g], Bi = ri4[g + 1];
#pragma unroll
        for (int kb = 0; kb < CTAP; kb += 4) {
            float4 Ce4 = re4[g + kb / 4 + 2];
            float4 Ci4 = ri4[g + kb / 4 + 2];
            float we[8] = {Ae.x, Ae.y, Ae.z, Ae.w, Be.x, Be.y, Be.z, Be.w};
            float wi[8] = {Ai.x, Ai.y, Ai.z, Ai.w, Bi.x, Bi.y, Bi.z, Bi.w};
#pragma unroll
            for (int u = 0; u < 4; u++) {
                float c0 = kes[kb + u], c1 = kis[kb + u];
                float c2 = ken[kb + u], c3 = kin[kb + u];
#pragma unroll
                for (int r = 0; r < 4; r++) {
                    float e = we[u + r], i2 = wi[u + r];
                    accs[r] = fmaf(c0, e, accs[r]);
                    accs[r] = fmaf(c1, i2, accs[r]);
                    accn[r] = fmaf(c2, e, accn[r]);
                    accn[r] = fmaf(c3, i2, accn[r]);
                }
            }
            Ae = Be; Be = Ce4; Ai = Bi; Bi = Ci4;
        }
        int j0 = g * 4;
#pragma unroll
        for (int r = 0; r < 4; r++) {
            shs[s][j0 + r] = accs[r];
            shn[s][j0 + r] = accn[r];
        }
    }
    __syncthreads();

    // recurrence: warps 0..3 cover 80 outputs (20 each, 12-lane halo)
    if (warp < 4) {
        const int t = t0 + warp * 20 + lane - 12;
        const int j = warp * 20 + lane + 1;
        const bool tin = (t >= 0);
        const bool rec = (t >= 1);

        float sn[SUB], ss[SUB];
#pragma unroll
        for (int q = 0; q < SUB; q++) {
            sn[q] = tin ? shn[q][j] : 0.f;
            ss[q] = tin ? shs[q][j] : 0.f;
        }
        float ssp0 = rec ? shs[0][j - 1] : 0.f;

        float sig[SUB], sigp[SUB];
#pragma unroll
        for (int q = 0; q < SUB; q++) {
            float r = 0.f;
#pragma unroll
            for (int qq = 0; qq < q; qq++) r += cw[q][qq] * sigp[qq];
            float x = sn[q] + thn[q] + (rec ? r : 0.f);
            sig[q] = sigm(x);
            sigp[q] = __shfl_up_sync(0xffffffffu, sig[q], 1);
        }

        if (lane >= 12 && t < T_DATA) {
            float* o = out + (size_t)t * (3 * SUB - 1);
            o[0] = sigm(ss[0] + ths[0]) * wsb[0];
#pragma unroll
            for (int q = 1; q < SUB; q++) o[q] = sig[q] * wsb[q];
#pragma unroll
            for (int q = 0; q < SUB; q++) o[SUB + q] = sig[q] * wnb[q];

            float ysp[SUB];
            ysp[0] = rec ? sigm(ssp0 + ths[0]) * wsb[0] : 0.f;
#pragma unroll
            for (int q = 1; q < SUB; q++) ysp[q] = rec ? sigp[q] * wsb[q] : 0.f;
#pragma unroll
            for (int i = 1; i < SUB; i++) {
                float x = ss[i] + ths[i];
#pragma unroll
                for (int qq = 0; qq < i; qq++) x = fmaf(cd[i][qq], ysp[qq], x);
                o[2 * SUB + (i - 1)] = sigm(x);
            }
        }
    }
}

// ---------------- launcher ----------------
extern "C" void kernel_launch(void* const* d_in, const int* in_sizes, int n_in,
                              void* d_out, int out_size) {
    const float* S_e      = (const float*)d_in[0];
    const float* S_i      = (const float*)d_in[1];
    const float* C_syn_e  = (const float*)d_in[2];
    const float* C_syn_i  = (const float*)d_in[3];
    const float* C_den    = (const float*)d_in[4];
    const float* W_s_syn  = (const float*)d_in[5];
    const float* W_ns_syn = (const float*)d_in[6];
    const float* Delta_s  = (const float*)d_in[7];
    const float* Delta_ns = (const float*)d_in[8];
    const float* Theta_s  = (const float*)d_in[9];
    const float* Theta_ns = (const float*)d_in[10];
    const float* W_s_sub  = (const float*)d_in[11];
    const float* W_ns_sub = (const float*)d_in[12];
    float* out = (float*)d_out;

    k_reduce<<<1250, 512>>>(S_e, S_i, C_syn_e, C_syn_i);
    k_fused<<<250, 288>>>(W_s_syn, W_ns_syn, Delta_s, Delta_ns,
                          C_den, Theta_s, Theta_ns, W_s_sub, W_ns_sub, out);
}

// round 9
// speedup vs baseline: 1.0432x; 1.0432x over previous
#include <cuda_runtime.h>

#define T_DATA 20000
#define E_NO   2000
#define I_NO   500
#define SUB    12
#define CTAP   40            // tail beyond lag 40 contributes < 3e-6 rel
#define TT     40            // fused outputs per block
#define INLEN  104           // staged IN length; i -> t = t0 - 52 + i (92 real, pad 104)
#define SYNLEN 56            // syn j -> t = t0 - 13 + j (53 used)
#define NTHR   192

__device__ unsigned g_mask_e[SUB][64];
__device__ unsigned g_mask_i[SUB][16];
__device__ float g_INe[SUB][T_DATA];
__device__ float g_INi[SUB][T_DATA];
__device__ __align__(16) float g_kers[SUB][4][CTAP];   // [s][e_s,i_s,e_ns,i_ns][m] reversed

__device__ __forceinline__ float sigm(float x) { return 1.f / (1.f + __expf(-x)); }

// ---------------- K0: pack connectivity (blocks 0-59) + build kernels (60-67) ------
// Pack: chunk (s, it): lane l loads float4 at elem it*128 + l*4; component c is bit l
// of word m = it*4 + c.
__global__ __launch_bounds__(128) void k_pack(const float* __restrict__ Ce,
                                              const float* __restrict__ Ci,
                                              const float* __restrict__ Ws_syn,
                                              const float* __restrict__ Wns_syn,
                                              const float* __restrict__ Ds,
                                              const float* __restrict__ Dns) {
    int lane = threadIdx.x & 31;
    if (blockIdx.x < 60) {
        int gw = blockIdx.x * 4 + (threadIdx.x >> 5);       // 240 chunk tasks
        if (gw < SUB * 16) {                                 // e-chunks
            int s = gw >> 4, it = gw & 15;
            int base = it * 128 + lane * 4;
            float4 v = (base < E_NO) ? *(const float4*)(Ce + s * E_NO + base)
                                     : make_float4(0.f, 0.f, 0.f, 0.f);
            unsigned m0 = __ballot_sync(0xffffffffu, v.x != 0.f);
            unsigned m1 = __ballot_sync(0xffffffffu, v.y != 0.f);
            unsigned m2 = __ballot_sync(0xffffffffu, v.z != 0.f);
            unsigned m3 = __ballot_sync(0xffffffffu, v.w != 0.f);
            if (lane == 0) *(uint4*)&g_mask_e[s][it * 4] = make_uint4(m0, m1, m2, m3);
        } else if (gw < SUB * 16 + SUB * 4) {                // i-chunks
            int j = gw - SUB * 16;
            int s = j >> 2, it = j & 3;
            int base = it * 128 + lane * 4;
            float4 v = (base < I_NO) ? *(const float4*)(Ci + s * I_NO + base)
                                     : make_float4(0.f, 0.f, 0.f, 0.f);
            unsigned m0 = __ballot_sync(0xffffffffu, v.x != 0.f);
            unsigned m1 = __ballot_sync(0xffffffffu, v.y != 0.f);
            unsigned m2 = __ballot_sync(0xffffffffu, v.z != 0.f);
            unsigned m3 = __ballot_sync(0xffffffffu, v.w != 0.f);
            if (lane == 0) *(uint4*)&g_mask_i[s][it * 4] = make_uint4(m0, m1, m2, m3);
        }
    } else {
        // kernel coefficient build: 1920 entries over 8 blocks x 128 threads x 2
        int base = (blockIdx.x - 60) * 128 + threadIdx.x;
#pragma unroll
        for (int p = 0; p < 2; p++) {
            int id = base + p * 1024;
            if (id < SUB * 4 * CTAP) {
                int s = id / (4 * CTAP), rem = id % (4 * CTAP);
                int c = rem / CTAP, m = rem % CTAP;
                int ch = c & 1;
                const float* W = (c >= 2) ? Wns_syn : Ws_syn;
                const float* D = (c >= 2) ? Dns : Ds;
                float fk = (float)(CTAP - 1 - m);            // reversed: idx m = lag CTAP-1-m
                float u = fmaxf(fk - expf(D[s * 2 + ch]), 0.f);
                float a = u, b = u * 0.60653065971f, cc = u * 0.36787944117f;
                ((float*)g_kers)[id] =
                    W[s * 6 + ch] * a * expf(-a) + W[s * 6 + 2 + ch] * b * expf(-b) +
                    W[s * 6 + 4 + ch] * cc * expf(-cc);
            }
        }
    }
}

// ---------------- K1: IN = S @ C.T, 512 thr/block, deep load batches ---------------
__global__ __launch_bounds__(512) void k_reduce(const float* __restrict__ Se,
                                                const float* __restrict__ Si) {
    __shared__ unsigned long long sme2[32][13];
    __shared__ unsigned long long smi2[8][13];
    for (int i = threadIdx.x; i < SUB * 32; i += blockDim.x) {
        int s = i >> 5, p = i & 31;
        sme2[p][s] = (unsigned long long)g_mask_e[s][2 * p] |
                     ((unsigned long long)g_mask_e[s][2 * p + 1] << 32);
    }
    for (int i = threadIdx.x; i < SUB * 8; i += blockDim.x) {
        int s = i >> 3, p = i & 7;
        smi2[p][s] = (unsigned long long)g_mask_i[s][2 * p] |
                     ((unsigned long long)g_mask_i[s][2 * p + 1] << 32);
    }
    __syncthreads();

    int warp = threadIdx.x >> 5, lane = threadIdx.x & 31;
    int row = blockIdx.x * 16 + warp;
    if (row >= T_DATA) return;

    const float* re = Se + (size_t)row * E_NO;
    const float* ri = Si + (size_t)row * I_NO;
    int acc_e = 0, acc_i = 0;

#pragma unroll
    for (int ob = 0; ob < 2; ob++) {
        float4 v[8];
#pragma unroll
        for (int q = 0; q < 8; q++) {
            int base = (ob * 8 + q) * 128 + lane * 4;
            v[q] = (base < E_NO) ? *(const float4*)(re + base)
                                 : make_float4(0.f, 0.f, 0.f, 0.f);
        }
#pragma unroll
        for (int q = 0; q < 8; q++) {
            int it = ob * 8 + q;
            unsigned m0 = __ballot_sync(0xffffffffu, v[q].x != 0.f);
            unsigned m1 = __ballot_sync(0xffffffffu, v[q].y != 0.f);
            unsigned m2 = __ballot_sync(0xffffffffu, v[q].z != 0.f);
            unsigned m3 = __ballot_sync(0xffffffffu, v[q].w != 0.f);
            if (lane < SUB) {
                unsigned long long A = (unsigned long long)m0 | ((unsigned long long)m1 << 32);
                unsigned long long B = (unsigned long long)m2 | ((unsigned long long)m3 << 32);
                acc_e += __popcll(A & sme2[it * 2 + 0][lane]);
                acc_e += __popcll(B & sme2[it * 2 + 1][lane]);
            }
        }
    }
    {
        float4 v[4];
#pragma unroll
        for (int q = 0; q < 4; q++) {
            int base = q * 128 + lane * 4;
            v[q] = (base < I_NO) ? *(const float4*)(ri + base)
                                 : make_float4(0.f, 0.f, 0.f, 0.f);
        }
#pragma unroll
        for (int q = 0; q < 4; q++) {
            unsigned m0 = __ballot_sync(0xffffffffu, v[q].x != 0.f);
            unsigned m1 = __ballot_sync(0xffffffffu, v[q].y != 0.f);
            unsigned m2 = __ballot_sync(0xffffffffu, v[q].z != 0.f);
            unsigned m3 = __ballot_sync(0xffffffffu, v[q].w != 0.f);
            if (lane < SUB) {
                unsigned long long A = (unsigned long long)m0 | ((unsigned long long)m1 << 32);
                unsigned long long B = (unsigned long long)m2 | ((unsigned long long)m3 << 32);
                acc_i += __popcll(A & smi2[q * 2 + 0][lane]);
                acc_i += __popcll(B & smi2[q * 2 + 1][lane]);
            }
        }
    }
    if (lane < SUB) {
        g_INe[lane][row] = (float)acc_e;
        g_INi[lane][row] = (float)acc_i;
    }
}

// ---------------- K2: fused conv(40 taps) + wavefront recurrence, TT=40 ------------
__global__ __launch_bounds__(NTHR) void k_fused(const float* __restrict__ C_den,
                                                const float* __restrict__ Ths_g,
                                                const float* __restrict__ Thns_g,
                                                const float* __restrict__ Ws_g,
                                                const float* __restrict__ Wns_g,
                                                float* __restrict__ out) {
    __shared__ __align__(16) float ker[SUB][4][CTAP];
    __shared__ __align__(16) float inbe[SUB][INLEN];
    __shared__ __align__(16) float inbi[SUB][INLEN];
    __shared__ float shs[SUB][SYNLEN], shn[SUB][SYNLEN];
    __shared__ float cw[SUB][SUB], cd[SUB][SUB];
    __shared__ float ths[SUB], thn[SUB], wsb[SUB], wnb[SUB];

    const int tid = threadIdx.x;
    const int warp = tid >> 5, lane = tid & 31;
    const int t0 = blockIdx.x * TT;

    // stage precomputed kernels: 1920 floats = 480 float4, coalesced
    {
        const float4* src = (const float4*)g_kers;
        float4* dst = (float4*)ker;
        for (int i = tid; i < SUB * 4 * CTAP / 4; i += NTHR) dst[i] = src[i];
    }
    if (tid < SUB * SUB) {
        float c = C_den[tid];
        cd[tid / SUB][tid % SUB] = c;
        cw[tid / SUB][tid % SUB] = c * Wns_g[tid % SUB];
    }
    if (tid < SUB) {
        ths[tid] = Ths_g[tid];
        thn[tid] = Thns_g[tid];
        wsb[tid] = Ws_g[tid];
        wnb[tid] = Wns_g[tid];
    }
    // stage IN: i in [0,104) -> t = t0 - 52 + i (92 real)
    for (int i = tid; i < SUB * INLEN; i += NTHR) {
        int s = i / INLEN, ii = i % INLEN;
        int g = t0 - 52 + ii;
        bool in = (g >= 0 && g < T_DATA && ii < 92);
        inbe[s][ii] = in ? g_INe[s][g] : 0.f;
        inbi[s][ii] = in ? g_INi[s][g] : 0.f;
    }
    __syncthreads();

    // conv: 168 threads = 12 subs x 14 groups of 4 outputs; syn[j] = sum_m ker[m]*IN[j+m]
    if (tid < SUB * 14) {
        int s = tid / 14, g = tid % 14;
        const float4* re4 = (const float4*)inbe[s];
        const float4* ri4 = (const float4*)inbi[s];
        const float4* kes = (const float4*)ker[s][0];
        const float4* kis = (const float4*)ker[s][1];
        const float4* ken = (const float4*)ker[s][2];
        const float4* kin = (const float4*)ker[s][3];

        float accs[4] = {0, 0, 0, 0}, accn[4] = {0, 0, 0, 0};
        float4 Ae = re4[g], Be = re4[g + 1];
        float4 Ai = ri4[g], Bi = ri4[g + 1];
#pragma unroll
        for (int kb4 = 0; kb4 < CTAP / 4; kb4++) {
            float4 Ce4 = re4[g + kb4 + 2];          // max idx 13+9+2=24 < 26
            float4 Ci4 = ri4[g + kb4 + 2];
            float4 c0v = kes[kb4], c1v = kis[kb4], c2v = ken[kb4], c3v = kin[kb4];
            float we[8] = {Ae.x, Ae.y, Ae.z, Ae.w, Be.x, Be.y, Be.z, Be.w};
            float wi[8] = {Ai.x, Ai.y, Ai.z, Ai.w, Bi.x, Bi.y, Bi.z, Bi.w};
            float c0a[4] = {c0v.x, c0v.y, c0v.z, c0v.w};
            float c1a[4] = {c1v.x, c1v.y, c1v.z, c1v.w};
            float c2a[4] = {c2v.x, c2v.y, c2v.z, c2v.w};
            float c3a[4] = {c3v.x, c3v.y, c3v.z, c3v.w};
#pragma unroll
            for (int u = 0; u < 4; u++) {
#pragma unroll
                for (int r = 0; r < 4; r++) {
                    float e = we[u + r], i2 = wi[u + r];
                    accs[r] = fmaf(c0a[u], e, accs[r]);
                    accs[r] = fmaf(c1a[u], i2, accs[r]);
                    accn[r] = fmaf(c2a[u], e, accn[r]);
                    accn[r] = fmaf(c3a[u], i2, accn[r]);
                }
            }
            Ae = Be; Be = Ce4; Ai = Bi; Bi = Ci4;
        }
        int j0 = g * 4;
#pragma unroll
        for (int r = 0; r < 4; r++) {
            shs[s][j0 + r] = accs[r];
            shn[s][j0 + r] = accn[r];
        }
    }
    __syncthreads();

    // recurrence: warps 0..1 cover 40 outputs (20 each, 12-lane halo)
    if (warp < 2) {
        const int t = t0 + warp * 20 + lane - 12;
        const int j = warp * 20 + lane + 1;
        const bool tin = (t >= 0);
        const bool rec = (t >= 1);

        float sn[SUB], ss[SUB];
#pragma unroll
        for (int q = 0; q < SUB; q++) {
            sn[q] = tin ? shn[q][j] : 0.f;
            ss[q] = tin ? shs[q][j] : 0.f;
        }
        float ssp0 = rec ? shs[0][j - 1] : 0.f;

        float sig[SUB], sigp[SUB];
#pragma unroll
        for (int q = 0; q < SUB; q++) {
            float r = 0.f;
#pragma unroll
            for (int qq = 0; qq < q; qq++) r += cw[q][qq] * sigp[qq];
            float x = sn[q] + thn[q] + (rec ? r : 0.f);
            sig[q] = sigm(x);
            sigp[q] = __shfl_up_sync(0xffffffffu, sig[q], 1);
        }

        if (lane >= 12 && t < T_DATA) {
            float* o = out + (size_t)t * (3 * SUB - 1);
            o[0] = sigm(ss[0] + ths[0]) * wsb[0];
#pragma unroll
            for (int q = 1; q < SUB; q++) o[q] = sig[q] * wsb[q];
#pragma unroll
            for (int q = 0; q < SUB; q++) o[SUB + q] = sig[q] * wnb[q];

            float ysp[SUB];
            ysp[0] = rec ? sigm(ssp0 + ths[0]) * wsb[0] : 0.f;
#pragma unroll
            for (int q = 1; q < SUB; q++) ysp[q] = rec ? sigp[q] * wsb[q] : 0.f;
#pragma unroll
            for (int i = 1; i < SUB; i++) {
                float x = ss[i] + ths[i];
#pragma unroll
                for (int qq = 0; qq < i; qq++) x = fmaf(cd[i][qq], ysp[qq], x);
                o[2 * SUB + (i - 1)] = sigm(x);
            }
        }
    }
}

// ---------------- launcher ----------------
extern "C" void kernel_launch(void* const* d_in, const int* in_sizes, int n_in,
                              void* d_out, int out_size) {
    const float* S_e      = (const float*)d_in[0];
    const float* S_i      = (const float*)d_in[1];
    const float* C_syn_e  = (const float*)d_in[2];
    const float* C_syn_i  = (const float*)d_in[3];
    const float* C_den    = (const float*)d_in[4];
    const float* W_s_syn  = (const float*)d_in[5];
    const float* W_ns_syn = (const float*)d_in[6];
    const float* Delta_s  = (const float*)d_in[7];
    const float* Delta_ns = (const float*)d_in[8];
    const float* Theta_s  = (const float*)d_in[9];
    const float* Theta_ns = (const float*)d_in[10];
    const float* W_s_sub  = (const float*)d_in[11];
    const float* W_ns_sub = (const float*)d_in[12];
    float* out = (float*)d_out;

    k_pack<<<68, 128>>>(C_syn_e, C_syn_i, W_s_syn, W_ns_syn, Delta_s, Delta_ns);
    k_reduce<<<1250, 512>>>(S_e, S_i);
    k_fused<<<T_DATA / TT, NTHR>>>(C_den, Theta_s, Theta_ns, W_s_sub, W_ns_sub, out);
}

// round 11
// speedup vs baseline: 1.0815x; 1.0367x over previous
#include <cuda_runtime.h>

#define T_DATA 20000
#define E_NO   2000
#define I_NO   500
#define SUB    12
#define CTAP   40            // tail beyond lag 40 contributes < 3e-6 rel
#define TT     140           // outputs per fused block -> 143 blocks (single wave)
#define INLEN  208           // staged IN; i -> t = t0 - 52 + i (196 real, pad 208)
#define SYNLEN 156           // syn j -> t = t0 - 13 + j (153 used)
#define NTHR   480

__device__ unsigned g_mask_e[SUB][64];
__device__ unsigned g_mask_i[SUB][16];
__device__ float g_INe[SUB][T_DATA];
__device__ float g_INi[SUB][T_DATA];

__device__ __forceinline__ float sigm(float x) { return 1.f / (1.f + __expf(-x)); }

// ---------------- K0: pack connectivity; 1 warp = 1 coalesced 512B chunk -> 4 words
__global__ __launch_bounds__(128) void k_pack(const float* __restrict__ Ce,
                                              const float* __restrict__ Ci) {
    int gw = blockIdx.x * 4 + (threadIdx.x >> 5);            // 240 chunk tasks
    int lane = threadIdx.x & 31;
    if (gw < SUB * 16) {                                     // e-chunks
        int s = gw >> 4, it = gw & 15;
        int base = it * 128 + lane * 4;
        float4 v = (base < E_NO) ? *(const float4*)(Ce + s * E_NO + base)
                                 : make_float4(0.f, 0.f, 0.f, 0.f);
        unsigned m0 = __ballot_sync(0xffffffffu, v.x != 0.f);
        unsigned m1 = __ballot_sync(0xffffffffu, v.y != 0.f);
        unsigned m2 = __ballot_sync(0xffffffffu, v.z != 0.f);
        unsigned m3 = __ballot_sync(0xffffffffu, v.w != 0.f);
        if (lane == 0) *(uint4*)&g_mask_e[s][it * 4] = make_uint4(m0, m1, m2, m3);
    } else if (gw < SUB * 16 + SUB * 4) {                    // i-chunks
        int j = gw - SUB * 16;
        int s = j >> 2, it = j & 3;
        int base = it * 128 + lane * 4;
        float4 v = (base < I_NO) ? *(const float4*)(Ci + s * I_NO + base)
                                 : make_float4(0.f, 0.f, 0.f, 0.f);
        unsigned m0 = __ballot_sync(0xffffffffu, v.x != 0.f);
        unsigned m1 = __ballot_sync(0xffffffffu, v.y != 0.f);
        unsigned m2 = __ballot_sync(0xffffffffu, v.z != 0.f);
        unsigned m3 = __ballot_sync(0xffffffffu, v.w != 0.f);
        if (lane == 0) *(uint4*)&g_mask_i[s][it * 4] = make_uint4(m0, m1, m2, m3);
    }
}

// ---------------- K1: IN = S @ C.T, 512 thr/block, deep load batches ---------------
__global__ __launch_bounds__(512) void k_reduce(const float* __restrict__ Se,
                                                const float* __restrict__ Si) {
    __shared__ unsigned long long sme2[32][13];
    __shared__ unsigned long long smi2[8][13];
    for (int i = threadIdx.x; i < SUB * 32; i += blockDim.x) {
        int s = i >> 5, p = i & 31;
        sme2[p][s] = (unsigned long long)g_mask_e[s][2 * p] |
                     ((unsigned long long)g_mask_e[s][2 * p + 1] << 32);
    }
    for (int i = threadIdx.x; i < SUB * 8; i += blockDim.x) {
        int s = i >> 3, p = i & 7;
        smi2[p][s] = (unsigned long long)g_mask_i[s][2 * p] |
                     ((unsigned long long)g_mask_i[s][2 * p + 1] << 32);
    }
    __syncthreads();

    int warp = threadIdx.x >> 5, lane = threadIdx.x & 31;
    int row = blockIdx.x * 16 + warp;
    if (row >= T_DATA) return;

    const float* re = Se + (size_t)row * E_NO;
    const float* ri = Si + (size_t)row * I_NO;
    int acc_e = 0, acc_i = 0;

#pragma unroll
    for (int ob = 0; ob < 2; ob++) {
        float4 v[8];
#pragma unroll
        for (int q = 0; q < 8; q++) {
            int base = (ob * 8 + q) * 128 + lane * 4;
            v[q] = (base < E_NO) ? *(const float4*)(re + base)
                                 : make_float4(0.f, 0.f, 0.f, 0.f);
        }
#pragma unroll
        for (int q = 0; q < 8; q++) {
            int it = ob * 8 + q;
            unsigned m0 = __ballot_sync(0xffffffffu, v[q].x != 0.f);
            unsigned m1 = __ballot_sync(0xffffffffu, v[q].y != 0.f);
            unsigned m2 = __ballot_sync(0xffffffffu, v[q].z != 0.f);
            unsigned m3 = __ballot_sync(0xffffffffu, v[q].w != 0.f);
            if (lane < SUB) {
                unsigned long long A = (unsigned long long)m0 | ((unsigned long long)m1 << 32);
                unsigned long long B = (unsigned long long)m2 | ((unsigned long long)m3 << 32);
                acc_e += __popcll(A & sme2[it * 2 + 0][lane]);
                acc_e += __popcll(B & sme2[it * 2 + 1][lane]);
            }
        }
    }
    {
        float4 v[4];
#pragma unroll
        for (int q = 0; q < 4; q++) {
            int base = q * 128 + lane * 4;
            v[q] = (base < I_NO) ? *(const float4*)(ri + base)
                                 : make_float4(0.f, 0.f, 0.f, 0.f);
        }
#pragma unroll
        for (int q = 0; q < 4; q++) {
            unsigned m0 = __ballot_sync(0xffffffffu, v[q].x != 0.f);
            unsigned m1 = __ballot_sync(0xffffffffu, v[q].y != 0.f);
            unsigned m2 = __ballot_sync(0xffffffffu, v[q].z != 0.f);
            unsigned m3 = __ballot_sync(0xffffffffu, v[q].w != 0.f);
            if (lane < SUB) {
                unsigned long long A = (unsigned long long)m0 | ((unsigned long long)m1 << 32);
                unsigned long long B = (unsigned long long)m2 | ((unsigned long long)m3 << 32);
                acc_i += __popcll(A & smi2[q * 2 + 0][lane]);
                acc_i += __popcll(B & smi2[q * 2 + 1][lane]);
            }
        }
    }
    if (lane < SUB) {
        g_INe[lane][row] = (float)acc_e;
        g_INi[lane][row] = (float)acc_i;
    }
}

// ---------------- K2: fused conv(40 taps) + recurrence, TT=140, single wave --------
__global__ __launch_bounds__(NTHR) void k_fused(const float* __restrict__ Ws_syn,
                                                const float* __restrict__ Wns_syn,
                                                const float* __restrict__ Ds,
                                                const float* __restrict__ Dns,
                                                const float* __restrict__ C_den,
                                                const float* __restrict__ Ths_g,
                                                const float* __restrict__ Thns_g,
                                                const float* __restrict__ Ws_g,
                                                const float* __restrict__ Wns_g,
                                                float* __restrict__ out) {
    __shared__ __align__(16) float ker[SUB][4][CTAP];       // reversed coeffs
    __shared__ __align__(16) float inbe[SUB][INLEN];
    __shared__ __align__(16) float inbi[SUB][INLEN];
    __shared__ float shs[SUB][SYNLEN], shn[SUB][SYNLEN];
    __shared__ float cw[SUB][SUB], cd[SUB][SUB];
    __shared__ float ths[SUB], thn[SUB], wsb[SUB], wnb[SUB];

    const int tid = threadIdx.x;
    const int warp = tid >> 5, lane = tid & 31;
    const int t0 = blockIdx.x * TT;

    // kernel coefficients: 1920 entries, 4 per thread
    for (int id = tid; id < SUB * 4 * CTAP; id += NTHR) {
        int s = id / (4 * CTAP), rem = id % (4 * CTAP);
        int c = rem / CTAP, m = rem % CTAP;
        int ch = c & 1;
        const float* W = (c >= 2) ? Wns_syn : Ws_syn;
        const float* D = (c >= 2) ? Dns : Ds;
        float fk = (float)(CTAP - 1 - m);                   // idx m = lag CTAP-1-m
        float u = fmaxf(fk - expf(D[s * 2 + ch]), 0.f);
        float a = u, b = u * 0.60653065971f, cc = u * 0.36787944117f;
        ker[s][c][m] = W[s * 6 + ch] * a * expf(-a) + W[s * 6 + 2 + ch] * b * expf(-b) +
                       W[s * 6 + 4 + ch] * cc * expf(-cc);
    }
    if (tid < SUB * SUB) {
        float c = C_den[tid];
        cd[tid / SUB][tid % SUB] = c;
        cw[tid / SUB][tid % SUB] = c * Wns_g[tid % SUB];
    }
    if (tid < SUB) {
        ths[tid] = Ths_g[tid];
        thn[tid] = Thns_g[tid];
        wsb[tid] = Ws_g[tid];
        wnb[tid] = Wns_g[tid];
    }
    // stage IN: i in [0,208) -> t = t0 - 52 + i (196 real)
    for (int i = tid; i < SUB * INLEN; i += NTHR) {
        int s = i / INLEN, ii = i % INLEN;
        int g = t0 - 52 + ii;
        bool in = (g >= 0 && g < T_DATA && ii < 196);
        inbe[s][ii] = in ? g_INe[s][g] : 0.f;
        inbi[s][ii] = in ? g_INi[s][g] : 0.f;
    }
    __syncthreads();

    // conv: 468 threads = 12 subs x 39 groups of 4; syn[j] = sum_m ker[m]*IN[j+m]
    if (tid < SUB * 39) {
        int s = tid / 39, g = tid % 39;
        const float4* re4 = (const float4*)inbe[s];
        const float4* ri4 = (const float4*)inbi[s];
        const float4* kes = (const float4*)ker[s][0];
        const float4* kis = (const float4*)ker[s][1];
        const float4* ken = (const float4*)ker[s][2];
        const float4* kin = (const float4*)ker[s][3];

        float accs[4] = {0, 0, 0, 0}, accn[4] = {0, 0, 0, 0};
        float4 Ae = re4[g], Be = re4[g + 1];
        float4 Ai = ri4[g], Bi = ri4[g + 1];
#pragma unroll
        for (int kb4 = 0; kb4 < CTAP / 4; kb4++) {
            float4 Ce4 = re4[g + kb4 + 2];                  // max 38+9+2 = 49 < 52
            float4 Ci4 = ri4[g + kb4 + 2];
            float4 c0v = kes[kb4], c1v = kis[kb4], c2v = ken[kb4], c3v = kin[kb4];
            float we[8] = {Ae.x, Ae.y, Ae.z, Ae.w, Be.x, Be.y, Be.z, Be.w};
            float wi[8] = {Ai.x, Ai.y, Ai.z, Ai.w, Bi.x, Bi.y, Bi.z, Bi.w};
            float c0a[4] = {c0v.x, c0v.y, c0v.z, c0v.w};
            float c1a[4] = {c1v.x, c1v.y, c1v.z, c1v.w};
            float c2a[4] = {c2v.x, c2v.y, c2v.z, c2v.w};
            float c3a[4] = {c3v.x, c3v.y, c3v.z, c3v.w};
#pragma unroll
            for (int u = 0; u < 4; u++) {
#pragma unroll
                for (int r = 0; r < 4; r++) {
                    float e = we[u + r], i2 = wi[u + r];
                    accs[r] = fmaf(c0a[u], e, accs[r]);
                    accs[r] = fmaf(c1a[u], i2, accs[r]);
                    accn[r] = fmaf(c2a[u], e, accn[r]);
                    accn[r] = fmaf(c3a[u], i2, accn[r]);
                }
            }
            Ae = Be; Be = Ce4; Ai = Bi; Bi = Ci4;
        }
        int j0 = g * 4;
#pragma unroll
        for (int r = 0; r < 4; r++) {
            shs[s][j0 + r] = accs[r];
            shn[s][j0 + r] = accn[r];
        }
    }
    __syncthreads();

    // recurrence: warps 0..6 cover 140 outputs (20 each, 12-lane halo)
    if (warp < 7) {
        const int t = t0 + warp * 20 + lane - 12;
        const int j = warp * 20 + lane + 1;                 // max 6*20+31+1 = 152 < 156
        const bool tin = (t >= 0);
        const bool rec = (t >= 1);

        float sn[SUB], ss[SUB];
#pragma unroll
        for (int q = 0; q < SUB; q++) {
            sn[q] = tin ? shn[q][j] : 0.f;
            ss[q] = tin ? shs[q][j] : 0.f;
        }
        float ssp0 = rec ? shs[0][j - 1] : 0.f;

        float sig[SUB], sigp[SUB];
#pragma unroll
        for (int q = 0; q < SUB; q++) {
            float r = 0.f;
#pragma unroll
            for (int qq = 0; qq < q; qq++) r += cw[q][qq] * sigp[qq];
            float x = sn[q] + thn[q] + (rec ? r : 0.f);
            sig[q] = sigm(x);
            sigp[q] = __shfl_up_sync(0xffffffffu, sig[q], 1);
        }

        if (lane >= 12 && t < T_DATA) {
            float* o = out + (size_t)t * (3 * SUB - 1);
            o[0] = sigm(ss[0] + ths[0]) * wsb[0];
#pragma unroll
            for (int q = 1; q < SUB; q++) o[q] = sig[q] * wsb[q];
#pragma unroll
            for (int q = 0; q < SUB; q++) o[SUB + q] = sig[q] * wnb[q];

            float ysp[SUB];
            ysp[0] = rec ? sigm(ssp0 + ths[0]) * wsb[0] : 0.f;
#pragma unroll
            for (int q = 1; q < SUB; q++) ysp[q] = rec ? sigp[q] * wsb[q] : 0.f;
#pragma unroll
            for (int i = 1; i < SUB; i++) {
                float x = ss[i] + ths[i];
#pragma unroll
                for (int qq = 0; qq < i; qq++) x = fmaf(cd[i][qq], ysp[qq], x);
                o[2 * SUB + (i - 1)] = sigm(x);
            }
        }
    }
}

// ---------------- launcher ----------------
extern "C" void kernel_launch(void* const* d_in, const int* in_sizes, int n_in,
                              void* d_out, int out_size) {
    const float* S_e      = (const float*)d_in[0];
    const float* S_i      = (const float*)d_in[1];
    const float* C_syn_e  = (const float*)d_in[2];
    const float* C_syn_i  = (const float*)d_in[3];
    const float* C_den    = (const float*)d_in[4];
    const float* W_s_syn  = (const float*)d_in[5];
    const float* W_ns_syn = (const float*)d_in[6];
    const float* Delta_s  = (const float*)d_in[7];
    const float* Delta_ns = (const float*)d_in[8];
    const float* Theta_s  = (const float*)d_in[9];
    const float* Theta_ns = (const float*)d_in[10];
    const float* W_s_sub  = (const float*)d_in[11];
    const float* W_ns_sub = (const float*)d_in[12];
    float* out = (float*)d_out;

    k_pack<<<60, 128>>>(C_syn_e, C_syn_i);
    k_reduce<<<1250, 512>>>(S_e, S_i);
    k_fused<<<(T_DATA + TT - 1) / TT, NTHR>>>(W_s_syn, W_ns_syn, Delta_s, Delta_ns,
                                              C_den, Theta_s, Theta_ns,
                                              W_s_sub, W_ns_sub, out);
}